// round 10
// baseline (speedup 1.0000x reference)
#include <cuda_runtime.h>
#include <cuda_bf16.h>

#define Nn 50000
#define Hh 128
#define Ee 400000
#define Gg 8
#define NB 391                 // ceil(Nn/128) tiles
#define GRIDX 296              // 148 SMs x 2 CTAs
#define NBLK (NB * 8)          // 3128 16-row blocks
#define APLANE (NBLK * 8 * 32) // uint4 count per plane
#define NSCAN 49               // ceil(Nn/1024)
typedef __nv_bfloat16 bf16;
typedef unsigned int u32;

// ---------------- scratch (static device globals; no allocation) ----------------
__device__ float d_h[Nn * Hh];
__device__ float d_tmp[Nn * Hh];
__device__ float d_cat[2 * Nn * Hh];        // Ps | Pd
__device__ float d_rm[Nn * Hh];             // mean message (pre-scaled)
__device__ uint4 d_afrag[2 * APLANE];       // enc hidden frags (hi | lo planes)
__device__ uint4 d_hfrag[2 * APLANE];       // h frags
__device__ bf16  d_imgh[7 * 128 * 128], d_imgl[7 * 128 * 128]; // W^T images [n][k]
__device__ int   d_cnt[Nn];
__device__ int   d_off[Nn + 1];
__device__ int   d_pos[Nn];
__device__ int   d_btot[NSCAN], d_boff[NSCAN];
__device__ float4 d_edata[Ee];              // {a0,a1,a2, src-bits} dst-sorted
__device__ float d_invcnt[Nn];
__device__ float d_gsum[Gg * Hh], d_bcsum[Gg * Hh], d_gcnt[Gg], d_bccnt[Gg];
__device__ float d_gproj[Gg * Hh], d_bcproj[Gg * Hh];
__device__ float d_Wmu[Hh * Hh];

// ---------------- helpers ----------------
__device__ __forceinline__ u32 smem_u32(const void* p) {
    u32 a;
    asm("{ .reg .u64 t; cvta.to.shared.u64 t, %1; cvt.u32.u64 %0, t; }" : "=r"(a) : "l"(p));
    return a;
}
__device__ __forceinline__ void ldsm_x4(u32* r, u32 addr) {
    asm volatile("ldmatrix.sync.aligned.m8n8.x4.shared.b16 {%0,%1,%2,%3}, [%4];"
                 : "=r"(r[0]), "=r"(r[1]), "=r"(r[2]), "=r"(r[3]) : "r"(addr));
}
__device__ __forceinline__ void mma16816(float* c, const u32* a, const u32* b) {
    asm volatile("mma.sync.aligned.m16n8k16.row.col.f32.bf16.bf16.f32 "
                 "{%0,%1,%2,%3}, {%4,%5,%6,%7}, {%8,%9}, {%0,%1,%2,%3};"
                 : "+f"(c[0]), "+f"(c[1]), "+f"(c[2]), "+f"(c[3])
                 : "r"(a[0]), "r"(a[1]), "r"(a[2]), "r"(a[3]), "r"(b[0]), "r"(b[1]));
}
__device__ __forceinline__ void split2(float v, unsigned short& h, unsigned short& l) {
    bf16 hh = __float2bfloat16(v);
    bf16 ll = __float2bfloat16(v - __bfloat162float(hh));
    h = __bfloat16_as_ushort(hh);
    l = __bfloat16_as_ushort(ll);
}
__device__ __forceinline__ uint2 split_pack(float2 v) {
    __nv_bfloat162 h2 = __float22bfloat162_rn(v);
    float2 hf = __bfloat1622float2(h2);
    __nv_bfloat162 l2 = __float22bfloat162_rn(make_float2(v.x - hf.x, v.y - hf.y));
    uint2 r;
    r.x = *(u32*)&h2;
    r.y = *(u32*)&l2;
    return r;
}

// ---------------- GEMM flags / smem layout ---------------------------------------
#define F_BIAS    1
#define F_RELU_O  8
#define F_WRITEC  16
#define F_EMIT    32

#define PAD_B 272
#define SM_B_HI 0
#define SM_B_LO (128 * PAD_B)
#define SMEMSZ  (2 * 128 * PAD_B)   // 69632 B

// UF3 smem layout: u frags [0,64K) alias B; half-B for pass3 above
#define U_HI   0
#define U_LO   32768
#define B3_HI  65536
#define B3_LO  (65536 + 64 * PAD_B)          // 82944
#define SMEMSZ3 (65536 + 2 * 64 * PAD_B)     // 100352 B

__device__ __forceinline__ void stageB(char* smem, int tid, const bf16* bh, const bf16* bl) {
#pragma unroll
    for (int i = 0; i < 8; i++) {
        int idx = tid + i * 256;
        int r = idx >> 4, c = idx & 15;
        *(uint4*)(smem + SM_B_HI + r * PAD_B + c * 16) = ((const uint4*)bh)[idx];
        *(uint4*)(smem + SM_B_LO + r * PAD_B + c * 16) = ((const uint4*)bl)[idx];
    }
}
// stage 64 rows of a B image into the B3 half region
__device__ __forceinline__ void stageB_half(char* smem, int tid, const bf16* bh, const bf16* bl) {
#pragma unroll
    for (int i = 0; i < 4; i++) {
        int idx = tid + i * 256;          // 0..1023 uint4 per plane
        int r = idx >> 4, c = idx & 15;
        *(uint4*)(smem + B3_HI + r * PAD_B + c * 16) = ((const uint4*)bh)[idx];
        *(uint4*)(smem + B3_LO + r * PAD_B + c * 16) = ((const uint4*)bl)[idx];
    }
}

// MMA pass with A from fragment-major planes (4M x 2N, acc[2][8][4])
__device__ __forceinline__ void frag_pass(
    float acc[2][8][4], const uint4* __restrict__ Af,
    int tile, int wm, u32 bbase4, u32 sb)
{
    const int lane = threadIdx.x & 31;
#pragma unroll
    for (int ks = 0; ks < 8; ks++) {
        u32 ah[2][4], al[2][4];
#pragma unroll
        for (int m = 0; m < 2; m++) {
            int idx = ((tile * 8 + wm * 2 + m) * 8 + ks) * 32 + lane;
            uint4 h4 = Af[idx];
            uint4 l4 = Af[APLANE + idx];
            ah[m][0] = h4.x; ah[m][1] = h4.y; ah[m][2] = h4.z; ah[m][3] = h4.w;
            al[m][0] = l4.x; al[m][1] = l4.y; al[m][2] = l4.z; al[m][3] = l4.w;
        }
#pragma unroll
        for (int nt2 = 0; nt2 < 4; nt2++) {
            u32 bh[4], bl[4];
            u32 bo = bbase4 + (u32)(nt2 * 16 * PAD_B) + (u32)(ks * 32);
            ldsm_x4(bh, sb + SM_B_HI + bo);
            ldsm_x4(bl, sb + SM_B_LO + bo);
#pragma unroll
            for (int m = 0; m < 2; m++) {
                mma16816(acc[m][2 * nt2 + 0], ah[m], bh);
                mma16816(acc[m][2 * nt2 + 1], ah[m], bh + 2);
                mma16816(acc[m][2 * nt2 + 0], al[m], bh);
                mma16816(acc[m][2 * nt2 + 1], al[m], bh + 2);
                mma16816(acc[m][2 * nt2 + 0], ah[m], bl);
                mma16816(acc[m][2 * nt2 + 1], ah[m], bl + 2);
            }
        }
    }
}

// MMA pass with A from fp32 (rm already mean-scaled by edge_agg)
__device__ __forceinline__ void a32_pass(
    float acc[2][8][4], const float* __restrict__ A32,
    int row0, int wm, int gid, int tig, u32 bbase4, u32 sb, int M)
{
    const float* pa[4];
#pragma unroll
    for (int j = 0; j < 4; j++) {
        int r = row0 + wm * 32 + j * 8 + gid;
        if (r > M - 1) r = M - 1;
        pa[j] = A32 + (size_t)r * Hh + tig * 2;
    }
#pragma unroll
    for (int ks = 0; ks < 8; ks++) {
        const int ko = ks * 16;
        u32 ah[2][4], al[2][4];
#pragma unroll
        for (int m = 0; m < 2; m++) {
            float2 v0 = *(const float2*)(pa[2 * m + 0] + ko);
            float2 v1 = *(const float2*)(pa[2 * m + 1] + ko);
            float2 v2 = *(const float2*)(pa[2 * m + 0] + ko + 8);
            float2 v3 = *(const float2*)(pa[2 * m + 1] + ko + 8);
            uint2 s0 = split_pack(v0), s1 = split_pack(v1);
            uint2 s2 = split_pack(v2), s3 = split_pack(v3);
            ah[m][0] = s0.x; al[m][0] = s0.y;
            ah[m][1] = s1.x; al[m][1] = s1.y;
            ah[m][2] = s2.x; al[m][2] = s2.y;
            ah[m][3] = s3.x; al[m][3] = s3.y;
        }
#pragma unroll
        for (int nt2 = 0; nt2 < 4; nt2++) {
            u32 bh[4], bl[4];
            u32 bo = bbase4 + (u32)(nt2 * 16 * PAD_B) + (u32)(ks * 32);
            ldsm_x4(bh, sb + SM_B_HI + bo);
            ldsm_x4(bl, sb + SM_B_LO + bo);
#pragma unroll
            for (int m = 0; m < 2; m++) {
                mma16816(acc[m][2 * nt2 + 0], ah[m], bh);
                mma16816(acc[m][2 * nt2 + 1], ah[m], bh + 2);
                mma16816(acc[m][2 * nt2 + 0], al[m], bh);
                mma16816(acc[m][2 * nt2 + 1], al[m], bh + 2);
                mma16816(acc[m][2 * nt2 + 0], ah[m], bl);
                mma16816(acc[m][2 * nt2 + 1], ah[m], bl + 2);
            }
        }
    }
}

// ---------------- generic GEMM (ENC / CAT / DEC) ----------------------------------
template<int FLAGS>
__global__ void __launch_bounds__(256, 2) gemm_tc(
    const uint4* __restrict__ Af,
    const bf16* __restrict__ B1h, const bf16* __restrict__ B1l,
    float* __restrict__ C, const float* __restrict__ bias,
    uint4* __restrict__ Ef, int M)
{
    extern __shared__ char smem[];
    const u32 sb = smem_u32(smem);
    const int tid = threadIdx.x;
    const int wid = tid >> 5, lane = tid & 31;
    const int yt = blockIdx.y;
    const bf16* b1h = B1h + yt * 16384;
    const bf16* b1l = B1l + yt * 16384;
    float* Cy = (FLAGS & F_WRITEC) ? C + (size_t)yt * M * Hh : nullptr;

    const int wm = wid & 3, wn = wid >> 2;
    const int gid = lane >> 2, tig = lane & 3;
    const u32 bbase4 = (u32)((wn * 64 + (lane & 7) + ((lane >> 4) << 3)) * PAD_B
                             + ((lane >> 3) & 1) * 16);

    stageB(smem, tid, b1h, b1l);
    __syncthreads();

    for (int tile = blockIdx.x; tile < NB; tile += gridDim.x) {
        const int row0 = tile * 128;
        float acc[2][8][4];
#pragma unroll
        for (int m = 0; m < 2; m++)
#pragma unroll
            for (int n = 0; n < 8; n++)
#pragma unroll
                for (int j = 0; j < 4; j++) acc[m][n][j] = 0.f;

        frag_pass(acc, Af, tile, wm, bbase4, sb);

#pragma unroll
        for (int m = 0; m < 2; m++) {
#pragma unroll
            for (int half = 0; half < 2; half++) {
                int grow = row0 + wm * 32 + m * 16 + half * 8 + gid;
                bool valid = grow < M;
#pragma unroll
                for (int nt = 0; nt < 8; nt++) {
                    int col = wn * 64 + nt * 8 + tig * 2;
                    float* a = &acc[m][nt][half * 2];
                    if (FLAGS & F_BIAS) {
                        float2 b2 = *(const float2*)(bias + col);
                        a[0] += b2.x; a[1] += b2.y;
                    }
                    if (FLAGS & F_RELU_O) {
                        a[0] = fmaxf(a[0], 0.f); a[1] = fmaxf(a[1], 0.f);
                    }
                    if ((FLAGS & F_WRITEC) && valid)
                        *(float2*)(Cy + (size_t)grow * Hh + col) = make_float2(a[0], a[1]);
                }
            }
        }
        if (FLAGS & F_EMIT) {
#pragma unroll
            for (int m = 0; m < 2; m++) {
                int mb = tile * 8 + wm * 2 + m;
                if (mb * 16 >= M) continue;
#pragma unroll
                for (int j = 0; j < 4; j++) {
                    int ksg = wn * 4 + j;
                    int idx = (mb * 8 + ksg) * 32 + lane;
                    uint2 s0 = split_pack(make_float2(acc[m][2 * j][0],     acc[m][2 * j][1]));
                    uint2 s1 = split_pack(make_float2(acc[m][2 * j][2],     acc[m][2 * j][3]));
                    uint2 s2 = split_pack(make_float2(acc[m][2 * j + 1][0], acc[m][2 * j + 1][1]));
                    uint2 s3 = split_pack(make_float2(acc[m][2 * j + 1][2], acc[m][2 * j + 1][3]));
                    Ef[idx]          = make_uint4(s0.x, s1.x, s2.x, s3.x);
                    Ef[APLANE + idx] = make_uint4(s0.y, s1.y, s2.y, s3.y);
                }
            }
        }
    }
}

// ---------------- fused UF3: u = relu(rm@Wmu + h@U_h + g); h += u@W_u2 ------------
__global__ void __launch_bounds__(256, 2) gemm_uf3(
    const uint4* __restrict__ Hf, const float* __restrict__ rm,
    const bf16* __restrict__ B1h, const bf16* __restrict__ B1l,   // Wmu
    const bf16* __restrict__ B2h, const bf16* __restrict__ B2l,   // U_h
    const bf16* __restrict__ B3h, const bf16* __restrict__ B3l,   // W_u2
    const float* __restrict__ bu2, const int* __restrict__ batch,
    float* __restrict__ H, uint4* __restrict__ Ef, int M)
{
    extern __shared__ char smem[];
    const u32 sb = smem_u32(smem);
    const int tid = threadIdx.x;
    const int wid = tid >> 5, lane = tid & 31;
    const int wm = wid & 3, wn = wid >> 2;
    const int gid = lane >> 2, tig = lane & 3;
    const u32 bbase4 = (u32)((wn * 64 + (lane & 7) + ((lane >> 4) << 3)) * PAD_B
                             + ((lane >> 3) & 1) * 16);
    const u32 bbase3 = (u32)((wn * 32 + (lane & 7) + ((lane >> 4) << 3)) * PAD_B
                             + ((lane >> 3) & 1) * 16);

    for (int tile = blockIdx.x; tile < NB; tile += gridDim.x) {
        const int row0 = tile * 128;
        __syncthreads();                       // prior tile's smem reads done
        stageB(smem, tid, B1h, B1l);
        __syncthreads();

        float acc[2][8][4];
#pragma unroll
        for (int m = 0; m < 2; m++)
#pragma unroll
            for (int n = 0; n < 8; n++)
#pragma unroll
                for (int j = 0; j < 4; j++) acc[m][n][j] = 0.f;

        a32_pass(acc, rm, row0, wm, gid, tig, bbase4, sb, M);
        __syncthreads();
        stageB(smem, tid, B2h, B2l);
        __syncthreads();
        frag_pass(acc, Hf, tile, wm, bbase4, sb);
        __syncthreads();                       // B reads done; smem reusable

        // u epilogue: + gproj[batch] + bcproj[batch], relu
#pragma unroll
        for (int m = 0; m < 2; m++) {
#pragma unroll
            for (int half = 0; half < 2; half++) {
                int grow = row0 + wm * 32 + m * 16 + half * 8 + gid;
                int g = (grow < M) ? batch[grow] : 0;
#pragma unroll
                for (int nt = 0; nt < 8; nt++) {
                    int col = wn * 64 + nt * 8 + tig * 2;
                    float* a = &acc[m][nt][half * 2];
                    float2 g2 = *(const float2*)(d_gproj + g * Hh + col);
                    float2 c2 = *(const float2*)(d_bcproj + g * Hh + col);
                    a[0] = fmaxf(a[0] + g2.x + c2.x, 0.f);
                    a[1] = fmaxf(a[1] + g2.y + c2.y, 0.f);
                }
            }
        }
        // store u frags into smem (fragment-major, local tile)
#pragma unroll
        for (int m = 0; m < 2; m++) {
#pragma unroll
            for (int j = 0; j < 4; j++) {
                int ksg = wn * 4 + j;
                int idx = ((wm * 2 + m) * 8 + ksg) * 32 + lane;
                uint2 s0 = split_pack(make_float2(acc[m][2 * j][0],     acc[m][2 * j][1]));
                uint2 s1 = split_pack(make_float2(acc[m][2 * j][2],     acc[m][2 * j][3]));
                uint2 s2 = split_pack(make_float2(acc[m][2 * j + 1][0], acc[m][2 * j + 1][1]));
                uint2 s3 = split_pack(make_float2(acc[m][2 * j + 1][2], acc[m][2 * j + 1][3]));
                *(uint4*)(smem + U_HI + idx * 16) = make_uint4(s0.x, s1.x, s2.x, s3.x);
                *(uint4*)(smem + U_LO + idx * 16) = make_uint4(s0.y, s1.y, s2.y, s3.y);
            }
        }

        // pass3: h' = h + u@W_u2 + bu2, two 64-col halves
#pragma unroll
        for (int hN = 0; hN < 2; hN++) {
            stageB_half(smem, tid, B3h + hN * 64 * 128, B3l + hN * 64 * 128);
            __syncthreads();                   // u-store + B3 stage visible

            float a3[2][4][4];
#pragma unroll
            for (int m = 0; m < 2; m++)
#pragma unroll
                for (int n = 0; n < 4; n++)
#pragma unroll
                    for (int j = 0; j < 4; j++) a3[m][n][j] = 0.f;

#pragma unroll
            for (int ks = 0; ks < 8; ks++) {
                u32 ah[2][4], al[2][4];
#pragma unroll
                for (int m = 0; m < 2; m++) {
                    int idx = ((wm * 2 + m) * 8 + ks) * 32 + lane;
                    uint4 h4 = *(const uint4*)(smem + U_HI + idx * 16);
                    uint4 l4 = *(const uint4*)(smem + U_LO + idx * 16);
                    ah[m][0] = h4.x; ah[m][1] = h4.y; ah[m][2] = h4.z; ah[m][3] = h4.w;
                    al[m][0] = l4.x; al[m][1] = l4.y; al[m][2] = l4.z; al[m][3] = l4.w;
                }
#pragma unroll
                for (int nt2 = 0; nt2 < 2; nt2++) {
                    u32 bh[4], bl[4];
                    u32 bo = bbase3 + (u32)(nt2 * 16 * PAD_B) + (u32)(ks * 32);
                    ldsm_x4(bh, sb + B3_HI + bo);
                    ldsm_x4(bl, sb + B3_LO + bo);
#pragma unroll
                    for (int m = 0; m < 2; m++) {
                        mma16816(a3[m][2 * nt2 + 0], ah[m], bh);
                        mma16816(a3[m][2 * nt2 + 1], ah[m], bh + 2);
                        mma16816(a3[m][2 * nt2 + 0], al[m], bh);
                        mma16816(a3[m][2 * nt2 + 1], al[m], bh + 2);
                        mma16816(a3[m][2 * nt2 + 0], ah[m], bl);
                        mma16816(a3[m][2 * nt2 + 1], ah[m], bl + 2);
                    }
                }
            }
            // h epilogue for this half
#pragma unroll
            for (int m = 0; m < 2; m++) {
#pragma unroll
                for (int half = 0; half < 2; half++) {
                    int grow = row0 + wm * 32 + m * 16 + half * 8 + gid;
                    if (grow >= M) continue;
#pragma unroll
                    for (int nt = 0; nt < 4; nt++) {
                        int col = hN * 64 + wn * 32 + nt * 8 + tig * 2;
                        float* a = &a3[m][nt][half * 2];
                        float2 b2 = *(const float2*)(bu2 + col);
                        float2 hv = *(const float2*)(H + (size_t)grow * Hh + col);
                        a[0] += b2.x + hv.x;
                        a[1] += b2.y + hv.y;
                        *(float2*)(H + (size_t)grow * Hh + col) = make_float2(a[0], a[1]);
                    }
                }
            }
            // emit hfrag for this half
#pragma unroll
            for (int m = 0; m < 2; m++) {
                int mb = tile * 8 + wm * 2 + m;
                if (mb * 16 >= M) continue;
#pragma unroll
                for (int j = 0; j < 2; j++) {
                    int colg = hN * 4 + wn * 2 + j;
                    int idx = (mb * 8 + colg) * 32 + lane;
                    uint2 s0 = split_pack(make_float2(a3[m][2 * j][0],     a3[m][2 * j][1]));
                    uint2 s1 = split_pack(make_float2(a3[m][2 * j][2],     a3[m][2 * j][3]));
                    uint2 s2 = split_pack(make_float2(a3[m][2 * j + 1][0], a3[m][2 * j + 1][1]));
                    uint2 s3 = split_pack(make_float2(a3[m][2 * j + 1][2], a3[m][2 * j + 1][3]));
                    Ef[idx]          = make_uint4(s0.x, s1.x, s2.x, s3.x);
                    Ef[APLANE + idx] = make_uint4(s0.y, s1.y, s2.y, s3.y);
                }
            }
            __syncthreads();                   // before next half restage
        }
    }
}

// ---------------- weight prep: W^T split into [n][k] images -------------------
__global__ void __launch_bounds__(256) prep_weights(
    const float* __restrict__ We2, const float* __restrict__ Wm1,
    const float* __restrict__ Wu1, const float* __restrict__ Wu2,
    const float* __restrict__ Wd1)
{
    int tile = blockIdx.y;
    int idx = blockIdx.x * 256 + threadIdx.x;
    int n = idx >> 7, k = idx & 127;
    float v = 0.f;
    switch (tile) {
        case 0: v = We2[(size_t)k * Hh + n]; break;
        case 1: v = Wm1[(size_t)k * Hh + n]; break;
        case 2: v = Wm1[(size_t)(128 + k) * Hh + n]; break;
        case 3: v = Wu1[(size_t)k * Hh + n]; break;           // U_h
        case 4: v = d_Wmu[(size_t)k * Hh + n]; break;         // W_m2 @ U_a
        case 5: v = Wu2[(size_t)k * Hh + n]; break;
        case 6: v = Wd1[(size_t)k * Hh + n]; break;
    }
    unsigned short h, l;
    split2(v, h, l);
    d_imgh[tile * 16384 + n * 128 + k] = __ushort_as_bfloat16(h);
    d_imgl[tile * 16384 + n * 128 + k] = __ushort_as_bfloat16(l);
}

// ---------------- encoder layer 1: warp-per-node frag emit --------------------
__global__ void __launch_bounds__(256) enc1_kernel(
    const float* __restrict__ x, const float* __restrict__ xmask,
    const float* __restrict__ We1, const float* __restrict__ be1)
{
    __shared__ float sW[8 * Hh];
    __shared__ float sb_[Hh];
    int tid = threadIdx.x;
    for (int i = tid; i < 8 * Hh; i += 256) sW[i] = We1[i];
    if (tid < Hh) sb_[tid] = be1[tid];
    __syncthreads();
    int lane = tid & 31;
    int warp = blockIdx.x * 8 + (tid >> 5);
    int nwarp = gridDim.x * 8;
    u32* Ah = (u32*)d_afrag;
    for (int v = warp; v < Nn; v += nwarp) {
        float t = 0.f;
        if (lane < 5)      t = x[v * 5 + lane];
        else if (lane < 8) t = xmask[v * 3 + (lane - 5)];
        float in[8];
#pragma unroll
        for (int k = 0; k < 8; k++) in[k] = __shfl_sync(0xffffffffu, t, k);
        int c0 = lane * 4;
        float s[4];
#pragma unroll
        for (int j = 0; j < 4; j++) {
            float acc = sb_[c0 + j];
#pragma unroll
            for (int k = 0; k < 8; k++) acc = fmaf(in[k], sW[k * Hh + c0 + j], acc);
            s[j] = fmaxf(acc, 0.f);
        }
        int blk = v >> 4, rloc = v & 15;
        int gid = rloc & 7, rsel = rloc >> 3;
#pragma unroll
        for (int p = 0; p < 2; p++) {
            uint2 sp = split_pack(make_float2(s[2 * p], s[2 * p + 1]));
            int c = lane * 2 + p;                 // pair index 0..63
            int ks = c >> 3, pc = c & 7;
            int khalf = pc >> 2, tg = pc & 3;
            int word = (((blk * 8 + ks) * 32) + gid * 4 + tg) * 4 + khalf * 2 + rsel;
            Ah[word] = sp.x;
            Ah[APLANE * 4 + word] = sp.y;
        }
    }
}

// ---------------- degree / CSR build (parallel scan) -----------------------------
__global__ void zero_cnt_kernel() {
    int i = blockIdx.x * blockDim.x + threadIdx.x;
    if (i < Nn) d_cnt[i] = 0;
}
__global__ void deg_kernel(const int* __restrict__ ei) {
    for (int e = blockIdx.x * blockDim.x + threadIdx.x; e < Ee; e += gridDim.x * blockDim.x)
        atomicAdd(&d_cnt[ei[Ee + e]], 1);
}
__global__ void invcnt_kernel() {
    int i = blockIdx.x * blockDim.x + threadIdx.x;
    if (i < Nn) d_invcnt[i] = 1.0f / (float)(d_cnt[i] + 1);
}
__global__ void __launch_bounds__(1024) scan1_kernel() {
    __shared__ int sh[1024];
    int tid = threadIdx.x;
    int i = blockIdx.x * 1024 + tid;
    int v = (i < Nn) ? d_cnt[i] : 0;
    sh[tid] = v;
    __syncthreads();
#pragma unroll
    for (int o = 1; o < 1024; o <<= 1) {
        int t = (tid >= o) ? sh[tid - o] : 0;
        __syncthreads();
        sh[tid] += t;
        __syncthreads();
    }
    if (i < Nn) { int e = sh[tid] - v; d_off[i] = e; d_pos[i] = e; }
    if (tid == 1023) d_btot[blockIdx.x] = sh[1023];
}
__global__ void scan2_kernel() {
    if (threadIdx.x == 0) {
        int run = 0;
        for (int b = 0; b < NSCAN; b++) { d_boff[b] = run; run += d_btot[b]; }
        d_off[Nn] = run;
    }
}
__global__ void scan3_kernel() {
    int i = blockIdx.x * blockDim.x + threadIdx.x;
    if (i < Nn) {
        int add = d_boff[i >> 10];
        d_off[i] += add;
        d_pos[i] += add;
    }
}
__global__ void scatter_kernel(const int* __restrict__ ei, const float* __restrict__ ea) {
    for (int e = blockIdx.x * blockDim.x + threadIdx.x; e < Ee; e += gridDim.x * blockDim.x) {
        int s = ei[e];
        int d = ei[Ee + e];
        int p = atomicAdd(&d_pos[d], 1);
        d_edata[p] = make_float4(__ldg(ea + 3 * e), __ldg(ea + 3 * e + 1),
                                 __ldg(ea + 3 * e + 2), __int_as_float(s));
    }
}

// ---------------- graph stats ---------------------------------------------------
__global__ void zero_stats_kernel() {
    int i = blockIdx.x * blockDim.x + threadIdx.x;
    if (i < Gg * Hh) { d_gsum[i] = 0.f; d_bcsum[i] = 0.f; }
    if (i < Gg) { d_gcnt[i] = 0.f; d_bccnt[i] = 0.f; }
}
__global__ void __launch_bounds__(128) init_stats_kernel(
    const float* __restrict__ xmask, const int* __restrict__ batch)
{
    int f = threadIdx.x;
    int v0 = blockIdx.x * 64;
    if (v0 >= Nn) return;
    float acc = 0.f, accbc = 0.f, cacc = 0.f, bcacc = 0.f;
    int cur = batch[v0];
    for (int i = 0; i < 64; i++) {
        int v = v0 + i; if (v >= Nn) break;
        int g = batch[v];
        if (g != cur) {
            atomicAdd(&d_gsum[cur * Hh + f], acc);
            atomicAdd(&d_bcsum[cur * Hh + f], accbc);
            if (f == 0) { atomicAdd(&d_gcnt[cur], cacc); atomicAdd(&d_bccnt[cur], bcacc); }
            acc = accbc = cacc = bcacc = 0.f; cur = g;
        }
        float hv = d_h[(size_t)v * Hh + f];
        float bc = __ldg(xmask + v * 3 + 2);
        acc += hv; accbc += hv * bc;
        if (f == 0) { cacc += 1.f; bcacc += bc; }
    }
    atomicAdd(&d_gsum[cur * Hh + f], acc);
    atomicAdd(&d_bcsum[cur * Hh + f], accbc);
    if (f == 0) { atomicAdd(&d_gcnt[cur], cacc); atomicAdd(&d_bccnt[cur], bcacc); }
}
__global__ void __launch_bounds__(128) graph_sum_kernel(const int* __restrict__ batch)
{
    int f = threadIdx.x;
    int v0 = blockIdx.x * 64;
    if (v0 >= Nn) return;
    float acc = 0.f;
    int cur = batch[v0];
    for (int i = 0; i < 64; i++) {
        int v = v0 + i; if (v >= Nn) break;
        int g = batch[v];
        if (g != cur) { atomicAdd(&d_gsum[cur * Hh + f], acc); acc = 0.f; cur = g; }
        acc += d_h[(size_t)v * Hh + f];
    }
    atomicAdd(&d_gsum[cur * Hh + f], acc);
}
// reads gsum, projects, then self-zeroes gsum for the next accumulation round
__global__ void __launch_bounds__(128) gproj_kernel(const float* __restrict__ Wu1)
{
    __shared__ float xg[Hh];
    int g = blockIdx.x, f = threadIdx.x;
    float c = fmaxf(d_gcnt[g], 1.f);
    xg[f] = d_gsum[g * Hh + f] / c;
    __syncthreads();
    d_gsum[g * Hh + f] = 0.f;
    float s = 0.f;
#pragma unroll 8
    for (int k = 0; k < Hh; k++) s = fmaf(xg[k], Wu1[(size_t)(256 + k) * Hh + f], s);
    d_gproj[g * Hh + f] = s;
}
__global__ void __launch_bounds__(128) bcproj_kernel(
    const float* __restrict__ Wu1, const float* __restrict__ bu1, const float* __restrict__ bm2)
{
    __shared__ float xbc[Hh];
    int g = blockIdx.x, f = threadIdx.x;
    float c = fmaxf(d_bccnt[g], 1.f);
    xbc[f] = d_bcsum[g * Hh + f] / c;
    __syncthreads();
    float s = bu1[f];
#pragma unroll 8
    for (int k = 0; k < Hh; k++) {
        s = fmaf(xbc[k],         Wu1[(size_t)(384 + k) * Hh + f], s);
        s = fmaf(__ldg(bm2 + k), Wu1[(size_t)(128 + k) * Hh + f], s);
    }
    d_bcproj[g * Hh + f] = s;
}
__global__ void __launch_bounds__(128) wmu_kernel(
    const float* __restrict__ Wm2, const float* __restrict__ Wu1)
{
    __shared__ float row[Hh];
    int k = blockIdx.x, f = threadIdx.x;
    row[f] = Wm2[(size_t)k * Hh + f];
    __syncthreads();
    float s = 0.f;
#pragma unroll 8
    for (int j = 0; j < Hh; j++) s = fmaf(row[j], Wu1[(size_t)(128 + j) * Hh + f], s);
    d_Wmu[(size_t)k * Hh + f] = s;
}

// ---------------- CSR edge aggregation: rm[d] = mean msgs (incl. self-loop) ------
__global__ void __launch_bounds__(256) edge_agg_kernel(
    const float* __restrict__ Wm1, const float* __restrict__ bm1)
{
    __shared__ float4 sW0[32], sW1[32], sW2[32], sB[32];
    int tid = threadIdx.x;
    if (tid < 32) {
        sW0[tid] = *(const float4*)(Wm1 + (size_t)256 * Hh + tid * 4);
        sW1[tid] = *(const float4*)(Wm1 + (size_t)257 * Hh + tid * 4);
        sW2[tid] = *(const float4*)(Wm1 + (size_t)258 * Hh + tid * 4);
        sB[tid]  = *(const float4*)(bm1 + tid * 4);
    }
    __syncthreads();
    int lane = tid & 31;
    int d = blockIdx.x * 8 + (tid >> 5);
    if (d >= Nn) return;
    float4 w0 = sW0[lane], w1 = sW1[lane], w2 = sW2[lane], bb = sB[lane];
    const float* Ps = d_cat;
    const float* Pd = d_cat + (size_t)Nn * Hh;
    float4 pd = *(const float4*)(Pd + (size_t)d * Hh + lane * 4);
    float4 pss = *(const float4*)(Ps + (size_t)d * Hh + lane * 4);
    float4 acc;
    acc.x = fmaxf(pss.x + pd.x + bb.x, 0.f);
    acc.y = fmaxf(pss.y + pd.y + bb.y, 0.f);
    acc.z = fmaxf(pss.z + pd.z + bb.z, 0.f);
    acc.w = fmaxf(pss.w + pd.w + bb.w, 0.f);
    int k0 = d_off[d], k1 = d_off[d + 1];
    for (int k = k0; k < k1; k++) {
        float4 md = __ldg(&d_edata[k]);
        int s = __float_as_int(md.w);
        float4 ps = *(const float4*)(Ps + (size_t)s * Hh + lane * 4);
        acc.x += fmaxf(ps.x + pd.x + md.x * w0.x + md.y * w1.x + md.z * w2.x + bb.x, 0.f);
        acc.y += fmaxf(ps.y + pd.y + md.x * w0.y + md.y * w1.y + md.z * w2.y + bb.y, 0.f);
        acc.z += fmaxf(ps.z + pd.z + md.x * w0.z + md.y * w1.z + md.z * w2.z + bb.z, 0.f);
        acc.w += fmaxf(ps.w + pd.w + md.x * w0.w + md.y * w1.w + md.z * w2.w + bb.w, 0.f);
    }
    float ic = d_invcnt[d];
    acc.x *= ic; acc.y *= ic; acc.z *= ic; acc.w *= ic;
    *(float4*)(d_rm + (size_t)d * Hh + lane * 4) = acc;
}

// ---------------- decoder layer 2 -------------------------------------------------
__global__ void __launch_bounds__(256) dec2_kernel(
    const float* __restrict__ Wd2, const float* __restrict__ bd2, float* __restrict__ out)
{
    int gt = blockIdx.x * blockDim.x + threadIdx.x;
    int w = gt >> 5, lane = gt & 31;
    if (w >= Nn) return;
    float4 v = ((const float4*)d_tmp)[(size_t)w * 32 + lane];
    float s0 = 0.f, s1 = 0.f, s2 = 0.f;
    int k0 = lane * 4;
    float av[4] = {v.x, v.y, v.z, v.w};
#pragma unroll
    for (int i = 0; i < 4; i++) {
        int k = k0 + i;
        float a = av[i];
        s0 = fmaf(a, __ldg(Wd2 + k * 3 + 0), s0);
        s1 = fmaf(a, __ldg(Wd2 + k * 3 + 1), s1);
        s2 = fmaf(a, __ldg(Wd2 + k * 3 + 2), s2);
    }
#pragma unroll
    for (int off = 16; off; off >>= 1) {
        s0 += __shfl_xor_sync(0xffffffffu, s0, off);
        s1 += __shfl_xor_sync(0xffffffffu, s1, off);
        s2 += __shfl_xor_sync(0xffffffffu, s2, off);
    }
    if (lane == 0) {
        out[w * 3 + 0] = s0 + __ldg(bd2 + 0);
        out[w * 3 + 1] = s1 + __ldg(bd2 + 1);
        out[w * 3 + 2] = s2 + __ldg(bd2 + 2);
    }
}

// ---------------- host orchestration ----------------------------------------------
#define FL_ENC (F_BIAS | F_WRITEC | F_EMIT)
#define FL_CAT (F_WRITEC)
#define FL_DEC (F_BIAS | F_RELU_O | F_WRITEC)

extern "C" void kernel_launch(void* const* d_in, const int* in_sizes, int n_in,
                              void* d_out, int out_size)
{
    const float* x     = (const float*)d_in[0];
    const float* xmask = (const float*)d_in[1];
    const float* ea    = (const float*)d_in[2];
    const float* We1 = (const float*)d_in[4];
    const float* be1 = (const float*)d_in[5];
    const float* We2 = (const float*)d_in[6];
    const float* be2 = (const float*)d_in[7];
    const float* Wm1 = (const float*)d_in[8];
    const float* bm1 = (const float*)d_in[9];
    const float* Wm2 = (const float*)d_in[10];
    const float* bm2 = (const float*)d_in[11];
    const float* Wu1 = (const float*)d_in[12];
    const float* bu1 = (const float*)d_in[13];
    const float* Wu2 = (const float*)d_in[14];
    const float* bu2 = (const float*)d_in[15];
    const float* Wd1 = (const float*)d_in[16];
    const float* bd1 = (const float*)d_in[17];
    const float* Wd2 = (const float*)d_in[18];
    const float* bd2 = (const float*)d_in[19];
    const int*   ei    = (const int*)d_in[20];
    const int*   batch = (const int*)d_in[21];
    float* out = (float*)d_out;

    float *p_h, *p_tmp, *p_cat, *p_rm;
    uint4 *p_af, *p_hf;
    bf16 *p_imgh, *p_imgl;
    cudaGetSymbolAddress((void**)&p_h,    d_h);
    cudaGetSymbolAddress((void**)&p_tmp,  d_tmp);
    cudaGetSymbolAddress((void**)&p_cat,  d_cat);
    cudaGetSymbolAddress((void**)&p_rm,   d_rm);
    cudaGetSymbolAddress((void**)&p_af,   d_afrag);
    cudaGetSymbolAddress((void**)&p_hf,   d_hfrag);
    cudaGetSymbolAddress((void**)&p_imgh, d_imgh);
    cudaGetSymbolAddress((void**)&p_imgl, d_imgl);

    cudaFuncSetAttribute(gemm_tc<FL_ENC>, cudaFuncAttributeMaxDynamicSharedMemorySize, SMEMSZ);
    cudaFuncSetAttribute(gemm_tc<FL_CAT>, cudaFuncAttributeMaxDynamicSharedMemorySize, SMEMSZ);
    cudaFuncSetAttribute(gemm_tc<FL_DEC>, cudaFuncAttributeMaxDynamicSharedMemorySize, SMEMSZ);
    cudaFuncSetAttribute(gemm_uf3, cudaFuncAttributeMaxDynamicSharedMemorySize, SMEMSZ3);

    // weight prep
    wmu_kernel<<<Hh, 128>>>(Wm2, Wu1);
    prep_weights<<<dim3(64, 7), 256>>>(We2, Wm1, Wu1, Wu2, Wd1);

    // encoder: enc1 -> afrag; h0 = enc_hidden @ We2 + be2 (write h + emit hfrag)
    enc1_kernel<<<512, 256>>>(x, xmask, We1, be1);
    gemm_tc<FL_ENC><<<dim3(GRIDX, 1), 256, SMEMSZ>>>(
        p_af, p_imgh, p_imgl, p_h, be2, p_hf, Nn);

    // degrees + CSR build (parallel scan)
    zero_cnt_kernel<<<(Nn + 255) / 256, 256>>>();
    deg_kernel<<<1024, 256>>>(ei);
    invcnt_kernel<<<(Nn + 255) / 256, 256>>>();
    scan1_kernel<<<NSCAN, 1024>>>();
    scan2_kernel<<<1, 32>>>();
    scan3_kernel<<<(Nn + 255) / 256, 256>>>();
    scatter_kernel<<<1024, 256>>>(ei, ea);

    // graph statistics from h0 + constant projections
    zero_stats_kernel<<<(Gg * Hh + 255) / 256, 256>>>();
    init_stats_kernel<<<(Nn + 63) / 64, 128>>>(xmask, batch);
    gproj_kernel<<<Gg, 128>>>(Wu1);   // also zeroes gsum for next round
    bcproj_kernel<<<Gg, 128>>>(Wu1, bu1, bm2);

    for (int r = 0; r < 3; r++) {
        // Ps|Pd = h @ [W_src | W_dst]
        gemm_tc<FL_CAT><<<dim3(GRIDX, 2), 256, SMEMSZ>>>(
            p_hf, p_imgh + 1 * 16384, p_imgl + 1 * 16384, p_cat, nullptr, nullptr, Nn);
        // rm[d] = mean over {self-loop + in-edges} of relu(Ps[src]+Pd[d]+ea@Wea+bm1)
        edge_agg_kernel<<<(Nn + 7) / 8, 256>>>(Wm1, bm1);
        // fused: u = relu(rm@Wmu + h@U_h + g-terms); h += u@W_u2 + bu2 (emit hfrag)
        gemm_uf3<<<GRIDX, 256, SMEMSZ3>>>(
            p_hf, p_rm,
            p_imgh + 4 * 16384, p_imgl + 4 * 16384,
            p_imgh + 3 * 16384, p_imgl + 3 * 16384,
            p_imgh + 5 * 16384, p_imgl + 5 * 16384,
            bu2, batch, p_h, p_hf, Nn);
        if (r < 2) {
            graph_sum_kernel<<<(Nn + 63) / 64, 128>>>(batch);
            gproj_kernel<<<Gg, 128>>>(Wu1);   // reads + self-zeroes gsum
        }
    }

    // decoder
    gemm_tc<FL_DEC><<<dim3(GRIDX, 1), 256, SMEMSZ>>>(
        p_hf, p_imgh + 6 * 16384, p_imgl + 6 * 16384, p_tmp, bd1, nullptr, Nn);
    dec2_kernel<<<(Nn * 32 + 255) / 256, 256>>>(Wd2, bd2, out);
}

// round 11
// speedup vs baseline: 1.3795x; 1.3795x over previous
#include <cuda_runtime.h>
#include <cuda_bf16.h>

#define Nn 50000
#define Hh 128
#define Ee 400000
#define Gg 8
#define NB 391                 // ceil(Nn/128) tiles
#define GRIDX 296              // 148 SMs x 2 CTAs
#define NBLK (NB * 8)          // 3128 16-row blocks
#define APLANE (NBLK * 8 * 32) // uint4 count per plane
#define NSCAN 49               // ceil(Nn/1024)
typedef __nv_bfloat16 bf16;
typedef unsigned int u32;

// ---------------- scratch (static device globals; no allocation) ----------------
__device__ float d_h[Nn * Hh];
__device__ float d_tmp[Nn * Hh];
__device__ float d_cat[2 * Nn * Hh];        // Ps | Pd
__device__ float d_rm[Nn * Hh];             // mean message (pre-scaled)
__device__ uint4 d_afrag[2 * APLANE];       // enc hidden frags (hi | lo planes)
__device__ uint4 d_bfrag[2 * APLANE];       // u frags
__device__ uint4 d_hfrag[2 * APLANE];       // h frags
__device__ bf16  d_imgh[7 * 128 * 128], d_imgl[7 * 128 * 128]; // W^T images [n][k]
__device__ int   d_cnt[Nn];
__device__ int   d_off[Nn + 1];
__device__ int   d_pos[Nn];
__device__ int   d_btot[NSCAN], d_boff[NSCAN];
__device__ float4 d_edata[Ee];              // {a0,a1,a2, src-bits} dst-sorted
__device__ float d_invcnt[Nn];
__device__ float d_gsum[Gg * Hh], d_bcsum[Gg * Hh], d_gcnt[Gg], d_bccnt[Gg];
__device__ float d_gproj[Gg * Hh], d_bcproj[Gg * Hh];
__device__ float d_Wmu[Hh * Hh];

// ---------------- helpers ----------------
__device__ __forceinline__ u32 smem_u32(const void* p) {
    u32 a;
    asm("{ .reg .u64 t; cvta.to.shared.u64 t, %1; cvt.u32.u64 %0, t; }" : "=r"(a) : "l"(p));
    return a;
}
__device__ __forceinline__ void ldsm_x4(u32* r, u32 addr) {
    asm volatile("ldmatrix.sync.aligned.m8n8.x4.shared.b16 {%0,%1,%2,%3}, [%4];"
                 : "=r"(r[0]), "=r"(r[1]), "=r"(r[2]), "=r"(r[3]) : "r"(addr));
}
__device__ __forceinline__ void mma16816(float* c, const u32* a, const u32* b) {
    asm volatile("mma.sync.aligned.m16n8k16.row.col.f32.bf16.bf16.f32 "
                 "{%0,%1,%2,%3}, {%4,%5,%6,%7}, {%8,%9}, {%0,%1,%2,%3};"
                 : "+f"(c[0]), "+f"(c[1]), "+f"(c[2]), "+f"(c[3])
                 : "r"(a[0]), "r"(a[1]), "r"(a[2]), "r"(a[3]), "r"(b[0]), "r"(b[1]));
}
__device__ __forceinline__ void split2(float v, unsigned short& h, unsigned short& l) {
    bf16 hh = __float2bfloat16(v);
    bf16 ll = __float2bfloat16(v - __bfloat162float(hh));
    h = __bfloat16_as_ushort(hh);
    l = __bfloat16_as_ushort(ll);
}
__device__ __forceinline__ uint2 split_pack(float2 v) {
    __nv_bfloat162 h2 = __float22bfloat162_rn(v);
    float2 hf = __bfloat1622float2(h2);
    __nv_bfloat162 l2 = __float22bfloat162_rn(make_float2(v.x - hf.x, v.y - hf.y));
    uint2 r;
    r.x = *(u32*)&h2;
    r.y = *(u32*)&l2;
    return r;
}

// ---------------- GEMM flags / smem layout (r9-identical) ------------------------
#define F_BIAS    1
#define F_ADDMAT  2
#define F_GRAPH   4
#define F_RELU_O  8
#define F_WRITEC  16
#define F_EMIT    32
#define F_PH2     64

#define PAD_B 272
#define SM_B_HI 0
#define SM_B_LO (128 * PAD_B)
#define SMEMSZ  (2 * 128 * PAD_B)   // 69632 B

__device__ __forceinline__ void stageB(char* smem, int tid, const bf16* bh, const bf16* bl) {
#pragma unroll
    for (int i = 0; i < 8; i++) {
        int idx = tid + i * 256;
        int r = idx >> 4, c = idx & 15;
        *(uint4*)(smem + SM_B_HI + r * PAD_B + c * 16) = ((const uint4*)bh)[idx];
        *(uint4*)(smem + SM_B_LO + r * PAD_B + c * 16) = ((const uint4*)bl)[idx];
    }
}

// MMA pass with A from fragment-major planes (4M x 2N, acc[2][8][4])
__device__ __forceinline__ void frag_pass(
    float acc[2][8][4], const uint4* __restrict__ Af,
    int tile, int wm, u32 bbase4, u32 sb)
{
    const int lane = threadIdx.x & 31;
#pragma unroll
    for (int ks = 0; ks < 8; ks++) {
        u32 ah[2][4], al[2][4];
#pragma unroll
        for (int m = 0; m < 2; m++) {
            int idx = ((tile * 8 + wm * 2 + m) * 8 + ks) * 32 + lane;
            uint4 h4 = Af[idx];
            uint4 l4 = Af[APLANE + idx];
            ah[m][0] = h4.x; ah[m][1] = h4.y; ah[m][2] = h4.z; ah[m][3] = h4.w;
            al[m][0] = l4.x; al[m][1] = l4.y; al[m][2] = l4.z; al[m][3] = l4.w;
        }
#pragma unroll
        for (int nt2 = 0; nt2 < 4; nt2++) {
            u32 bh[4], bl[4];
            u32 bo = bbase4 + (u32)(nt2 * 16 * PAD_B) + (u32)(ks * 32);
            ldsm_x4(bh, sb + SM_B_HI + bo);
            ldsm_x4(bl, sb + SM_B_LO + bo);
#pragma unroll
            for (int m = 0; m < 2; m++) {
                mma16816(acc[m][2 * nt2 + 0], ah[m], bh);
                mma16816(acc[m][2 * nt2 + 1], ah[m], bh + 2);
                mma16816(acc[m][2 * nt2 + 0], al[m], bh);
                mma16816(acc[m][2 * nt2 + 1], al[m], bh + 2);
                mma16816(acc[m][2 * nt2 + 0], ah[m], bl);
                mma16816(acc[m][2 * nt2 + 1], ah[m], bl + 2);
            }
        }
    }
}

// MMA pass with A from fp32 (rm already mean-scaled by edge_agg)
__device__ __forceinline__ void a32_pass(
    float acc[2][8][4], const float* __restrict__ A32,
    int row0, int wm, int gid, int tig, u32 bbase4, u32 sb, int M)
{
    const float* pa[4];
#pragma unroll
    for (int j = 0; j < 4; j++) {
        int r = row0 + wm * 32 + j * 8 + gid;
        if (r > M - 1) r = M - 1;
        pa[j] = A32 + (size_t)r * Hh + tig * 2;
    }
#pragma unroll
    for (int ks = 0; ks < 8; ks++) {
        const int ko = ks * 16;
        u32 ah[2][4], al[2][4];
#pragma unroll
        for (int m = 0; m < 2; m++) {
            float2 v0 = *(const float2*)(pa[2 * m + 0] + ko);
            float2 v1 = *(const float2*)(pa[2 * m + 1] + ko);
            float2 v2 = *(const float2*)(pa[2 * m + 0] + ko + 8);
            float2 v3 = *(const float2*)(pa[2 * m + 1] + ko + 8);
            uint2 s0 = split_pack(v0), s1 = split_pack(v1);
            uint2 s2 = split_pack(v2), s3 = split_pack(v3);
            ah[m][0] = s0.x; al[m][0] = s0.y;
            ah[m][1] = s1.x; al[m][1] = s1.y;
            ah[m][2] = s2.x; al[m][2] = s2.y;
            ah[m][3] = s3.x; al[m][3] = s3.y;
        }
#pragma unroll
        for (int nt2 = 0; nt2 < 4; nt2++) {
            u32 bh[4], bl[4];
            u32 bo = bbase4 + (u32)(nt2 * 16 * PAD_B) + (u32)(ks * 32);
            ldsm_x4(bh, sb + SM_B_HI + bo);
            ldsm_x4(bl, sb + SM_B_LO + bo);
#pragma unroll
            for (int m = 0; m < 2; m++) {
                mma16816(acc[m][2 * nt2 + 0], ah[m], bh);
                mma16816(acc[m][2 * nt2 + 1], ah[m], bh + 2);
                mma16816(acc[m][2 * nt2 + 0], al[m], bh);
                mma16816(acc[m][2 * nt2 + 1], al[m], bh + 2);
                mma16816(acc[m][2 * nt2 + 0], ah[m], bl);
                mma16816(acc[m][2 * nt2 + 1], ah[m], bl + 2);
            }
        }
    }
}

template<int FLAGS>
__global__ void __launch_bounds__(256, 2) gemm_tc(
    const uint4* __restrict__ Af, const float* __restrict__ A32,
    const bf16* __restrict__ B1h, const bf16* __restrict__ B1l,
    const bf16* __restrict__ B2h, const bf16* __restrict__ B2l,
    float* __restrict__ C, const float* __restrict__ bias,
    const float* __restrict__ addmat, const int* __restrict__ batch,
    uint4* __restrict__ Ef, int M)
{
    extern __shared__ char smem[];
    const u32 sb = smem_u32(smem);
    const int tid = threadIdx.x;
    const int wid = tid >> 5, lane = tid & 31;
    const int yt = blockIdx.y;
    const bf16* b1h = B1h + yt * 16384;
    const bf16* b1l = B1l + yt * 16384;
    float* Cy = (FLAGS & F_WRITEC) ? C + (size_t)yt * M * Hh : nullptr;

    const int wm = wid & 3;            // 4 warps in M (32 rows each)
    const int wn = wid >> 2;           // 2 warps in N (64 cols each)
    const int gid = lane >> 2, tig = lane & 3;
    const u32 bbase4 = (u32)((wn * 64 + (lane & 7) + ((lane >> 4) << 3)) * PAD_B
                             + ((lane >> 3) & 1) * 16);

    if (!(FLAGS & F_PH2)) {
        stageB(smem, tid, b1h, b1l);
        __syncthreads();
    }

    for (int tile = blockIdx.x; tile < NB; tile += gridDim.x) {
        const int row0 = tile * 128;

        float acc[2][8][4];
#pragma unroll
        for (int m = 0; m < 2; m++)
#pragma unroll
            for (int n = 0; n < 8; n++)
#pragma unroll
                for (int j = 0; j < 4; j++) acc[m][n][j] = 0.f;

        if (FLAGS & F_PH2) {
            __syncthreads();
            stageB(smem, tid, b1h, b1l);
            __syncthreads();
            a32_pass(acc, A32, row0, wm, gid, tig, bbase4, sb, M);
            __syncthreads();
            stageB(smem, tid, B2h, B2l);
            __syncthreads();
            frag_pass(acc, Af, tile, wm, bbase4, sb);
        } else {
            frag_pass(acc, Af, tile, wm, bbase4, sb);
        }

        if (FLAGS & (F_BIAS | F_ADDMAT | F_GRAPH | F_RELU_O)) {
#pragma unroll
            for (int m = 0; m < 2; m++) {
#pragma unroll
                for (int half = 0; half < 2; half++) {
                    int grow = row0 + wm * 32 + m * 16 + half * 8 + gid;
                    bool valid = grow < M;
                    int g = 0;
                    if ((FLAGS & F_GRAPH) && valid) g = batch[grow];
#pragma unroll
                    for (int nt = 0; nt < 8; nt++) {
                        int col = wn * 64 + nt * 8 + tig * 2;
                        float* a = &acc[m][nt][half * 2];
                        if (FLAGS & F_BIAS) {
                            float2 b2 = *(const float2*)(bias + col);
                            a[0] += b2.x; a[1] += b2.y;
                        }
                        if ((FLAGS & F_ADDMAT) && valid) {
                            float2 m2 = *(const float2*)(addmat + (size_t)grow * Hh + col);
                            a[0] += m2.x; a[1] += m2.y;
                        }
                        if ((FLAGS & F_GRAPH) && valid) {
                            float2 g2 = *(const float2*)(d_gproj + g * Hh + col);
                            float2 c2 = *(const float2*)(d_bcproj + g * Hh + col);
                            a[0] += g2.x + c2.x; a[1] += g2.y + c2.y;
                        }
                        if (FLAGS & F_RELU_O) {
                            a[0] = fmaxf(a[0], 0.f); a[1] = fmaxf(a[1], 0.f);
                        }
                    }
                }
            }
        }

        if (FLAGS & F_WRITEC) {
#pragma unroll
            for (int m = 0; m < 2; m++) {
#pragma unroll
                for (int half = 0; half < 2; half++) {
                    int grow = row0 + wm * 32 + m * 16 + half * 8 + gid;
                    if (grow >= M) continue;
#pragma unroll
                    for (int nt = 0; nt < 8; nt++) {
                        int col = wn * 64 + nt * 8 + tig * 2;
                        *(float2*)(Cy + (size_t)grow * Hh + col) =
                            make_float2(acc[m][nt][half * 2], acc[m][nt][half * 2 + 1]);
                    }
                }
            }
        }

        if (FLAGS & F_EMIT) {
#pragma unroll
            for (int m = 0; m < 2; m++) {
                int mb = tile * 8 + wm * 2 + m;
                if (mb * 16 >= M) continue;
#pragma unroll
                for (int j = 0; j < 4; j++) {
                    int ksg = wn * 4 + j;
                    int idx = (mb * 8 + ksg) * 32 + lane;
                    uint2 s0 = split_pack(make_float2(acc[m][2 * j][0],     acc[m][2 * j][1]));
                    uint2 s1 = split_pack(make_float2(acc[m][2 * j][2],     acc[m][2 * j][3]));
                    uint2 s2 = split_pack(make_float2(acc[m][2 * j + 1][0], acc[m][2 * j + 1][1]));
                    uint2 s3 = split_pack(make_float2(acc[m][2 * j + 1][2], acc[m][2 * j + 1][3]));
                    Ef[idx]          = make_uint4(s0.x, s1.x, s2.x, s3.x);
                    Ef[APLANE + idx] = make_uint4(s0.y, s1.y, s2.y, s3.y);
                }
            }
        }
    }
}

// ---------------- weight prep: W^T split into [n][k] images -------------------
__global__ void __launch_bounds__(256) prep_weights(
    const float* __restrict__ We2, const float* __restrict__ Wm1,
    const float* __restrict__ Wu1, const float* __restrict__ Wu2,
    const float* __restrict__ Wd1)
{
    int tile = blockIdx.y;
    int idx = blockIdx.x * 256 + threadIdx.x;
    int n = idx >> 7, k = idx & 127;
    float v = 0.f;
    switch (tile) {
        case 0: v = We2[(size_t)k * Hh + n]; break;
        case 1: v = Wm1[(size_t)k * Hh + n]; break;
        case 2: v = Wm1[(size_t)(128 + k) * Hh + n]; break;
        case 3: v = Wu1[(size_t)k * Hh + n]; break;           // U_h
        case 4: v = d_Wmu[(size_t)k * Hh + n]; break;         // W_m2 @ U_a
        case 5: v = Wu2[(size_t)k * Hh + n]; break;
        case 6: v = Wd1[(size_t)k * Hh + n]; break;
    }
    unsigned short h, l;
    split2(v, h, l);
    d_imgh[tile * 16384 + n * 128 + k] = __ushort_as_bfloat16(h);
    d_imgl[tile * 16384 + n * 128 + k] = __ushort_as_bfloat16(l);
}

// ---------------- encoder layer 1: frag emit (r9 block-per-node) --------------
__global__ void __launch_bounds__(128) enc1_kernel(
    const float* __restrict__ x, const float* __restrict__ xmask,
    const float* __restrict__ We1, const float* __restrict__ be1)
{
    __shared__ float sW[8 * Hh];
    __shared__ float sb_[Hh];
    __shared__ float in[8];
    int f = threadIdx.x;
#pragma unroll
    for (int k = 0; k < 8; k++) sW[k * Hh + f] = We1[k * Hh + f];
    sb_[f] = be1[f];
    __syncthreads();
    u32* Ah = (u32*)d_afrag;
    for (int v = blockIdx.x; v < Nn; v += gridDim.x) {
        if (f < 5)      in[f] = x[v * 5 + f];
        else if (f < 8) in[f] = xmask[v * 3 + (f - 5)];
        __syncthreads();
        float s = sb_[f];
#pragma unroll
        for (int k = 0; k < 8; k++) s = fmaf(in[k], sW[k * Hh + f], s);
        s = fmaxf(s, 0.f);
        float s2 = __shfl_xor_sync(0xffffffffu, s, 1);
        if (!(f & 1)) {
            uint2 sp = split_pack(make_float2(s, s2));
            int c = f >> 1;
            int ks = c >> 3, pc = c & 7;
            int khalf = pc >> 2, tg = pc & 3;
            int blk = v >> 4, rloc = v & 15;
            int gid = rloc & 7, rsel = rloc >> 3;
            int word = (((blk * 8 + ks) * 32) + gid * 4 + tg) * 4 + khalf * 2 + rsel;
            Ah[word] = sp.x;
            Ah[APLANE * 4 + word] = sp.y;
        }
        __syncthreads();
    }
}

// ---------------- degree / CSR build (parallel scan) -----------------------------
__global__ void zero_cnt_kernel() {
    int i = blockIdx.x * blockDim.x + threadIdx.x;
    if (i < Nn) d_cnt[i] = 0;
}
__global__ void deg_kernel(const int* __restrict__ ei) {
    for (int e = blockIdx.x * blockDim.x + threadIdx.x; e < Ee; e += gridDim.x * blockDim.x)
        atomicAdd(&d_cnt[ei[Ee + e]], 1);
}
__global__ void invcnt_kernel() {
    int i = blockIdx.x * blockDim.x + threadIdx.x;
    if (i < Nn) d_invcnt[i] = 1.0f / (float)(d_cnt[i] + 1);
}
__global__ void __launch_bounds__(1024) scan1_kernel() {
    __shared__ int sh[1024];
    int tid = threadIdx.x;
    int i = blockIdx.x * 1024 + tid;
    int v = (i < Nn) ? d_cnt[i] : 0;
    sh[tid] = v;
    __syncthreads();
#pragma unroll
    for (int o = 1; o < 1024; o <<= 1) {
        int t = (tid >= o) ? sh[tid - o] : 0;
        __syncthreads();
        sh[tid] += t;
        __syncthreads();
    }
    if (i < Nn) { int e = sh[tid] - v; d_off[i] = e; d_pos[i] = e; }
    if (tid == 1023) d_btot[blockIdx.x] = sh[1023];
}
__global__ void __launch_bounds__(64) scan2_kernel() {
    __shared__ int sh[64];
    int tid = threadIdx.x;
    int v = (tid < NSCAN) ? d_btot[tid] : 0;
    sh[tid] = v;
    __syncthreads();
#pragma unroll
    for (int o = 1; o < 64; o <<= 1) {
        int t = (tid >= o) ? sh[tid - o] : 0;
        __syncthreads();
        sh[tid] += t;
        __syncthreads();
    }
    if (tid < NSCAN) d_boff[tid] = sh[tid] - v;   // exclusive
    if (tid == NSCAN - 1) d_off[Nn] = sh[tid];
}
__global__ void scan3_kernel() {
    int i = blockIdx.x * blockDim.x + threadIdx.x;
    if (i < Nn) {
        int add = d_boff[i >> 10];
        d_off[i] += add;
        d_pos[i] += add;
    }
}
__global__ void scatter_kernel(const int* __restrict__ ei, const float* __restrict__ ea) {
    for (int e = blockIdx.x * blockDim.x + threadIdx.x; e < Ee; e += gridDim.x * blockDim.x) {
        int s = ei[e];
        int d = ei[Ee + e];
        int p = atomicAdd(&d_pos[d], 1);
        d_edata[p] = make_float4(__ldg(ea + 3 * e), __ldg(ea + 3 * e + 1),
                                 __ldg(ea + 3 * e + 2), __int_as_float(s));
    }
}

// ---------------- graph stats ---------------------------------------------------
__global__ void zero_stats_kernel() {
    int i = blockIdx.x * blockDim.x + threadIdx.x;
    if (i < Gg * Hh) { d_gsum[i] = 0.f; d_bcsum[i] = 0.f; }
    if (i < Gg) { d_gcnt[i] = 0.f; d_bccnt[i] = 0.f; }
}
__global__ void __launch_bounds__(128) init_stats_kernel(
    const float* __restrict__ xmask, const int* __restrict__ batch)
{
    int f = threadIdx.x;
    int v0 = blockIdx.x * 64;
    if (v0 >= Nn) return;
    float acc = 0.f, accbc = 0.f, cacc = 0.f, bcacc = 0.f;
    int cur = batch[v0];
    for (int i = 0; i < 64; i++) {
        int v = v0 + i; if (v >= Nn) break;
        int g = batch[v];
        if (g != cur) {
            atomicAdd(&d_gsum[cur * Hh + f], acc);
            atomicAdd(&d_bcsum[cur * Hh + f], accbc);
            if (f == 0) { atomicAdd(&d_gcnt[cur], cacc); atomicAdd(&d_bccnt[cur], bcacc); }
            acc = accbc = cacc = bcacc = 0.f; cur = g;
        }
        float hv = d_h[(size_t)v * Hh + f];
        float bc = __ldg(xmask + v * 3 + 2);
        acc += hv; accbc += hv * bc;
        if (f == 0) { cacc += 1.f; bcacc += bc; }
    }
    atomicAdd(&d_gsum[cur * Hh + f], acc);
    atomicAdd(&d_bcsum[cur * Hh + f], accbc);
    if (f == 0) { atomicAdd(&d_gcnt[cur], cacc); atomicAdd(&d_bccnt[cur], bcacc); }
}
__global__ void __launch_bounds__(128) graph_sum_kernel(const int* __restrict__ batch)
{
    int f = threadIdx.x;
    int v0 = blockIdx.x * 64;
    if (v0 >= Nn) return;
    float acc = 0.f;
    int cur = batch[v0];
    for (int i = 0; i < 64; i++) {
        int v = v0 + i; if (v >= Nn) break;
        int g = batch[v];
        if (g != cur) { atomicAdd(&d_gsum[cur * Hh + f], acc); acc = 0.f; cur = g; }
        acc += d_h[(size_t)v * Hh + f];
    }
    atomicAdd(&d_gsum[cur * Hh + f], acc);
}
// reads gsum, projects, then self-zeroes gsum for the next accumulation round
__global__ void __launch_bounds__(128) gproj_kernel(const float* __restrict__ Wu1)
{
    __shared__ float xg[Hh];
    int g = blockIdx.x, f = threadIdx.x;
    float c = fmaxf(d_gcnt[g], 1.f);
    xg[f] = d_gsum[g * Hh + f] / c;
    __syncthreads();
    d_gsum[g * Hh + f] = 0.f;
    float s = 0.f;
#pragma unroll 8
    for (int k = 0; k < Hh; k++) s = fmaf(xg[k], Wu1[(size_t)(256 + k) * Hh + f], s);
    d_gproj[g * Hh + f] = s;
}
__global__ void __launch_bounds__(128) bcproj_kernel(
    const float* __restrict__ Wu1, const float* __restrict__ bu1, const float* __restrict__ bm2)
{
    __shared__ float xbc[Hh];
    int g = blockIdx.x, f = threadIdx.x;
    float c = fmaxf(d_bccnt[g], 1.f);
    xbc[f] = d_bcsum[g * Hh + f] / c;
    __syncthreads();
    float s = bu1[f];
#pragma unroll 8
    for (int k = 0; k < Hh; k++) {
        s = fmaf(xbc[k],         Wu1[(size_t)(384 + k) * Hh + f], s);
        s = fmaf(__ldg(bm2 + k), Wu1[(size_t)(128 + k) * Hh + f], s);
    }
    d_bcproj[g * Hh + f] = s;
}
__global__ void __launch_bounds__(128) wmu_kernel(
    const float* __restrict__ Wm2, const float* __restrict__ Wu1)
{
    __shared__ float row[Hh];
    int k = blockIdx.x, f = threadIdx.x;
    row[f] = Wm2[(size_t)k * Hh + f];
    __syncthreads();
    float s = 0.f;
#pragma unroll 8
    for (int j = 0; j < Hh; j++) s = fmaf(row[j], Wu1[(size_t)(128 + j) * Hh + f], s);
    d_Wmu[(size_t)k * Hh + f] = s;
}

// ---------------- CSR edge aggregation: rm[d] = mean msgs (incl. self-loop) ------
__global__ void __launch_bounds__(256) edge_agg_kernel(
    const float* __restrict__ Wm1, const float* __restrict__ bm1)
{
    __shared__ float4 sW0[32], sW1[32], sW2[32], sB[32];
    int tid = threadIdx.x;
    if (tid < 32) {
        sW0[tid] = *(const float4*)(Wm1 + (size_t)256 * Hh + tid * 4);
        sW1[tid] = *(const float4*)(Wm1 + (size_t)257 * Hh + tid * 4);
        sW2[tid] = *(const float4*)(Wm1 + (size_t)258 * Hh + tid * 4);
        sB[tid]  = *(const float4*)(bm1 + tid * 4);
    }
    __syncthreads();
    int lane = tid & 31;
    int d = blockIdx.x * 8 + (tid >> 5);
    if (d >= Nn) return;
    float4 w0 = sW0[lane], w1 = sW1[lane], w2 = sW2[lane], bb = sB[lane];
    const float* Ps = d_cat;
    const float* Pd = d_cat + (size_t)Nn * Hh;
    float4 pd = *(const float4*)(Pd + (size_t)d * Hh + lane * 4);
    float4 pss = *(const float4*)(Ps + (size_t)d * Hh + lane * 4);
    float4 acc;
    acc.x = fmaxf(pss.x + pd.x + bb.x, 0.f);
    acc.y = fmaxf(pss.y + pd.y + bb.y, 0.f);
    acc.z = fmaxf(pss.z + pd.z + bb.z, 0.f);
    acc.w = fmaxf(pss.w + pd.w + bb.w, 0.f);
    int k0 = d_off[d], k1 = d_off[d + 1];
    for (int k = k0; k < k1; k++) {
        float4 md = __ldg(&d_edata[k]);
        int s = __float_as_int(md.w);
        float4 ps = *(const float4*)(Ps + (size_t)s * Hh + lane * 4);
        acc.x += fmaxf(ps.x + pd.x + md.x * w0.x + md.y * w1.x + md.z * w2.x + bb.x, 0.f);
        acc.y += fmaxf(ps.y + pd.y + md.x * w0.y + md.y * w1.y + md.z * w2.y + bb.y, 0.f);
        acc.z += fmaxf(ps.z + pd.z + md.x * w0.z + md.y * w1.z + md.z * w2.z + bb.z, 0.f);
        acc.w += fmaxf(ps.w + pd.w + md.x * w0.w + md.y * w1.w + md.z * w2.w + bb.w, 0.f);
    }
    float ic = d_invcnt[d];
    acc.x *= ic; acc.y *= ic; acc.z *= ic; acc.w *= ic;
    *(float4*)(d_rm + (size_t)d * Hh + lane * 4) = acc;
}

// ---------------- decoder layer 2 -------------------------------------------------
__global__ void __launch_bounds__(256) dec2_kernel(
    const float* __restrict__ Wd2, const float* __restrict__ bd2, float* __restrict__ out)
{
    int gt = blockIdx.x * blockDim.x + threadIdx.x;
    int w = gt >> 5, lane = gt & 31;
    if (w >= Nn) return;
    float4 v = ((const float4*)d_tmp)[(size_t)w * 32 + lane];
    float s0 = 0.f, s1 = 0.f, s2 = 0.f;
    int k0 = lane * 4;
    float av[4] = {v.x, v.y, v.z, v.w};
#pragma unroll
    for (int i = 0; i < 4; i++) {
        int k = k0 + i;
        float a = av[i];
        s0 = fmaf(a, __ldg(Wd2 + k * 3 + 0), s0);
        s1 = fmaf(a, __ldg(Wd2 + k * 3 + 1), s1);
        s2 = fmaf(a, __ldg(Wd2 + k * 3 + 2), s2);
    }
#pragma unroll
    for (int off = 16; off; off >>= 1) {
        s0 += __shfl_xor_sync(0xffffffffu, s0, off);
        s1 += __shfl_xor_sync(0xffffffffu, s1, off);
        s2 += __shfl_xor_sync(0xffffffffu, s2, off);
    }
    if (lane == 0) {
        out[w * 3 + 0] = s0 + __ldg(bd2 + 0);
        out[w * 3 + 1] = s1 + __ldg(bd2 + 1);
        out[w * 3 + 2] = s2 + __ldg(bd2 + 2);
    }
}

// ---------------- host orchestration ----------------------------------------------
#define FL_ENC (F_BIAS | F_WRITEC | F_EMIT)
#define FL_CAT (F_WRITEC)
#define FL_UF  (F_PH2 | F_GRAPH | F_RELU_O | F_EMIT)
#define FL_H   (F_BIAS | F_ADDMAT | F_WRITEC | F_EMIT)
#define FL_DEC (F_BIAS | F_RELU_O | F_WRITEC)

extern "C" void kernel_launch(void* const* d_in, const int* in_sizes, int n_in,
                              void* d_out, int out_size)
{
    const float* x     = (const float*)d_in[0];
    const float* xmask = (const float*)d_in[1];
    const float* ea    = (const float*)d_in[2];
    const float* We1 = (const float*)d_in[4];
    const float* be1 = (const float*)d_in[5];
    const float* We2 = (const float*)d_in[6];
    const float* be2 = (const float*)d_in[7];
    const float* Wm1 = (const float*)d_in[8];
    const float* bm1 = (const float*)d_in[9];
    const float* Wm2 = (const float*)d_in[10];
    const float* bm2 = (const float*)d_in[11];
    const float* Wu1 = (const float*)d_in[12];
    const float* bu1 = (const float*)d_in[13];
    const float* Wu2 = (const float*)d_in[14];
    const float* bu2 = (const float*)d_in[15];
    const float* Wd1 = (const float*)d_in[16];
    const float* bd1 = (const float*)d_in[17];
    const float* Wd2 = (const float*)d_in[18];
    const float* bd2 = (const float*)d_in[19];
    const int*   ei    = (const int*)d_in[20];
    const int*   batch = (const int*)d_in[21];
    float* out = (float*)d_out;

    float *p_h, *p_tmp, *p_cat, *p_rm;
    uint4 *p_af, *p_bf, *p_hf;
    bf16 *p_imgh, *p_imgl;
    cudaGetSymbolAddress((void**)&p_h,    d_h);
    cudaGetSymbolAddress((void**)&p_tmp,  d_tmp);
    cudaGetSymbolAddress((void**)&p_cat,  d_cat);
    cudaGetSymbolAddress((void**)&p_rm,   d_rm);
    cudaGetSymbolAddress((void**)&p_af,   d_afrag);
    cudaGetSymbolAddress((void**)&p_bf,   d_bfrag);
    cudaGetSymbolAddress((void**)&p_hf,   d_hfrag);
    cudaGetSymbolAddress((void**)&p_imgh, d_imgh);
    cudaGetSymbolAddress((void**)&p_imgl, d_imgl);

    cudaFuncSetAttribute(gemm_tc<FL_ENC>, cudaFuncAttributeMaxDynamicSharedMemorySize, SMEMSZ);
    cudaFuncSetAttribute(gemm_tc<FL_CAT>, cudaFuncAttributeMaxDynamicSharedMemorySize, SMEMSZ);
    cudaFuncSetAttribute(gemm_tc<FL_UF>,  cudaFuncAttributeMaxDynamicSharedMemorySize, SMEMSZ);
    cudaFuncSetAttribute(gemm_tc<FL_H>,   cudaFuncAttributeMaxDynamicSharedMemorySize, SMEMSZ);
    cudaFuncSetAttribute(gemm_tc<FL_DEC>, cudaFuncAttributeMaxDynamicSharedMemorySize, SMEMSZ);

    // weight prep
    wmu_kernel<<<Hh, 128>>>(Wm2, Wu1);
    prep_weights<<<dim3(64, 7), 256>>>(We2, Wm1, Wu1, Wu2, Wd1);

    // encoder: enc1 -> afrag; h0 = enc_hidden @ We2 + be2 (write h + emit hfrag)
    enc1_kernel<<<2048, 128>>>(x, xmask, We1, be1);
    gemm_tc<FL_ENC><<<dim3(GRIDX, 1), 256, SMEMSZ>>>(
        p_af, nullptr, p_imgh, p_imgl, nullptr, nullptr,
        p_h, be2, nullptr, nullptr, p_hf, Nn);

    // degrees + CSR build (parallel scan; edges constant per launch)
    zero_cnt_kernel<<<(Nn + 255) / 256, 256>>>();
    deg_kernel<<<1024, 256>>>(ei);
    invcnt_kernel<<<(Nn + 255) / 256, 256>>>();
    scan1_kernel<<<NSCAN, 1024>>>();
    scan2_kernel<<<1, 64>>>();
    scan3_kernel<<<(Nn + 255) / 256, 256>>>();
    scatter_kernel<<<1024, 256>>>(ei, ea);

    // graph statistics from h0 + constant projections
    zero_stats_kernel<<<(Gg * Hh + 255) / 256, 256>>>();
    init_stats_kernel<<<(Nn + 63) / 64, 128>>>(xmask, batch);
    gproj_kernel<<<Gg, 128>>>(Wu1);   // reads + self-zeroes gsum
    bcproj_kernel<<<Gg, 128>>>(Wu1, bu1, bm2);

    for (int r = 0; r < 3; r++) {
        // Ps|Pd = h @ [W_src | W_dst]
        gemm_tc<FL_CAT><<<dim3(GRIDX, 2), 256, SMEMSZ>>>(
            p_hf, nullptr, p_imgh + 1 * 16384, p_imgl + 1 * 16384, nullptr, nullptr,
            p_cat, nullptr, nullptr, nullptr, nullptr, Nn);
        // rm[d] = mean over {self-loop + in-edges} of relu(Ps[src]+Pd[d]+ea@Wea+bm1)
        edge_agg_kernel<<<(Nn + 7) / 8, 256>>>(Wm1, bm1);
        // u = relu( rm@Wmu + h@U_h + gproj + bcproj ) -> bfrag (K=256 fused)
        gemm_tc<FL_UF><<<dim3(GRIDX, 1), 256, SMEMSZ>>>(
            p_hf, p_rm, p_imgh + 4 * 16384, p_imgl + 4 * 16384,
            p_imgh + 3 * 16384, p_imgl + 3 * 16384,
            nullptr, nullptr, nullptr, batch, p_bf, Nn);
        // h = h + u@W_u2 + b_u2 (write h + emit hfrag)
        gemm_tc<FL_H><<<dim3(GRIDX, 1), 256, SMEMSZ>>>(
            p_bf, nullptr, p_imgh + 5 * 16384, p_imgl + 5 * 16384, nullptr, nullptr,
            p_h, bu2, p_h, nullptr, p_hf, Nn);
        if (r < 2) {
            graph_sum_kernel<<<(Nn + 63) / 64, 128>>>(batch);
            gproj_kernel<<<Gg, 128>>>(Wu1);   // reads + self-zeroes gsum
        }
    }

    // decoder
    gemm_tc<FL_DEC><<<dim3(GRIDX, 1), 256, SMEMSZ>>>(
        p_hf, nullptr, p_imgh + 6 * 16384, p_imgl + 6 * 16384, nullptr, nullptr,
        p_tmp, bd1, nullptr, nullptr, nullptr, Nn);
    dec2_kernel<<<(Nn * 32 + 255) / 256, 256>>>(Wd2, bd2, out);
}